// round 7
// baseline (speedup 1.0000x reference)
#include <cuda_runtime.h>
#include <cuda_bf16.h>
#include <cstdint>

#define BATCH 16
#define CDIM 256
#define HWDIM 2304
#define PB (CDIM * HWDIM)

#define NST 3
#define STG_B 61440u                // A(128x80B x2) + B(256x80B x2)
#define SMEM_B (NST * STG_B)        // 184320

// ---------------------------------------------------------------------------
// Device scratch (allocation-free)
// ---------------------------------------------------------------------------
__device__ float g_inv[BATCH];
__device__ float g_T[(size_t)BATCH * PB];
__device__ __align__(1024) __nv_bfloat16 g_Xhi[(size_t)BATCH * PB];
__device__ __align__(1024) __nv_bfloat16 g_Xlo[(size_t)BATCH * PB];
__device__ __align__(1024) __nv_bfloat16 g_XThi[(size_t)BATCH * PB];
__device__ __align__(1024) __nv_bfloat16 g_XTlo[(size_t)BATCH * PB];
__device__ __align__(1024) __nv_bfloat16 g_Whi[CDIM * CDIM];
__device__ __align__(1024) __nv_bfloat16 g_Wlo[CDIM * CDIM];
__device__ __align__(1024) __nv_bfloat16 g_Shi[(size_t)BATCH * HWDIM * HWDIM];
__device__ __align__(1024) __nv_bfloat16 g_Slo[(size_t)BATCH * HWDIM * HWDIM];
__device__ __align__(1024) __nv_bfloat16 g_TThi[(size_t)BATCH * PB];
__device__ __align__(1024) __nv_bfloat16 g_TTlo[(size_t)BATCH * PB];

// ---------------------------------------------------------------------------
// per-batch 1/||x||^2
// ---------------------------------------------------------------------------
__global__ void sumsq_kernel(const float* __restrict__ x) {
    const int b = blockIdx.x;
    const float4* p = (const float4*)(x + (size_t)b * PB);
    float s = 0.f;
    for (int i = threadIdx.x; i < PB / 4; i += blockDim.x) {
        float4 v = p[i];
        s += v.x * v.x + v.y * v.y + v.z * v.z + v.w * v.w;
    }
    __shared__ float red[512];
    red[threadIdx.x] = s;
    __syncthreads();
    for (int off = blockDim.x >> 1; off > 0; off >>= 1) {
        if (threadIdx.x < (unsigned)off) red[threadIdx.x] += red[threadIdx.x + off];
        __syncthreads();
    }
    if (threadIdx.x == 0) g_inv[b] = 1.0f / red[0];
}

// ---------------------------------------------------------------------------
// f32 -> bf16 hi/lo split (flat)
// ---------------------------------------------------------------------------
__device__ __forceinline__ uint32_t packbf(float a, float b) {
    __nv_bfloat16 ha = __float2bfloat16(a), hb = __float2bfloat16(b);
    return (uint32_t)__bfloat16_as_ushort(ha) | ((uint32_t)__bfloat16_as_ushort(hb) << 16);
}
__global__ void split_flat(const float4* __restrict__ in,
                           uint2* __restrict__ hi, uint2* __restrict__ lo, int n4) {
    int i = blockIdx.x * blockDim.x + threadIdx.x;
    if (i >= n4) return;
    float4 v = in[i];
    __nv_bfloat16 h0 = __float2bfloat16(v.x), h1 = __float2bfloat16(v.y);
    __nv_bfloat16 h2 = __float2bfloat16(v.z), h3 = __float2bfloat16(v.w);
    uint2 hp, lp;
    hp.x = (uint32_t)__bfloat16_as_ushort(h0) | ((uint32_t)__bfloat16_as_ushort(h1) << 16);
    hp.y = (uint32_t)__bfloat16_as_ushort(h2) | ((uint32_t)__bfloat16_as_ushort(h3) << 16);
    lp.x = packbf(v.x - __bfloat162float(h0), v.y - __bfloat162float(h1));
    lp.y = packbf(v.z - __bfloat162float(h2), v.w - __bfloat162float(h3));
    hi[i] = hp;
    lo[i] = lp;
}

// ---------------------------------------------------------------------------
// per-batch transpose + split: in [rows,cols] f32 -> out [cols,rows] bf16 hi/lo
// ---------------------------------------------------------------------------
__global__ void transpose_split(const float* __restrict__ in,
                                __nv_bfloat16* __restrict__ hi,
                                __nv_bfloat16* __restrict__ lo,
                                int rows, int cols) {
    __shared__ float t[32][33];
    const size_t off = (size_t)blockIdx.z * rows * cols;
    const int c0 = blockIdx.x * 32, r0 = blockIdx.y * 32;
    const int x = threadIdx.x, y0 = threadIdx.y;
#pragma unroll
    for (int yy = y0; yy < 32; yy += 8)
        t[yy][x] = in[off + (size_t)(r0 + yy) * cols + c0 + x];
    __syncthreads();
#pragma unroll
    for (int yy = y0; yy < 32; yy += 8) {
        float v = t[x][yy];
        __nv_bfloat16 h = __float2bfloat16(v);
        size_t o = off + (size_t)(c0 + yy) * rows + r0 + x;
        hi[o] = h;
        lo[o] = __float2bfloat16(v - __bfloat162float(h));
    }
}

// ---------------------------------------------------------------------------
// PTX helpers (sm_80 baseline — compile on plain compute_103)
// ---------------------------------------------------------------------------
__device__ __forceinline__ uint32_t s2u(const void* p) {
    uint32_t a;
    asm("{ .reg .u64 t; cvta.to.shared.u64 t, %1; cvt.u32.u64 %0, t; }" : "=r"(a) : "l"(p));
    return a;
}
__device__ __forceinline__ void cp16(uint32_t d, const void* g) {
    asm volatile("cp.async.cg.shared.global [%0], [%1], 16;" :: "r"(d), "l"(g));
}
#define LDM4(r, addr) \
    asm volatile("ldmatrix.sync.aligned.m8n8.x4.shared.b16 {%0,%1,%2,%3}, [%4];" \
        : "=r"((r)[0]), "=r"((r)[1]), "=r"((r)[2]), "=r"((r)[3]) : "r"(addr))
#define MMA16816(c, a0, a1, a2, a3, b0, b1) \
    asm volatile("mma.sync.aligned.m16n8k16.row.col.f32.bf16.bf16.f32 " \
        "{%0,%1,%2,%3}, {%4,%5,%6,%7}, {%8,%9}, {%0,%1,%2,%3};" \
        : "+f"((c)[0]), "+f"((c)[1]), "+f"((c)[2]), "+f"((c)[3]) \
        : "r"(a0), "r"(a1), "r"(a2), "r"(a3), "r"(b0), "r"(b1))

// ---------------------------------------------------------------------------
// bf16 mma.sync GEMM, CTA 128x256, warp tile 64x64, KC=32, 3-term emulation
//   D[m,n] = sum_k A[m,k]*B[n,k]   (A:[M,K], B:[N,K], both K-major bf16 hi/lo)
// Stage layout: Ah@0 (128x80B), Al@10240, Bh@20480 (256x80B), Bl@40960
// EPI 0: S = relu(acc*g_inv[bz])^2 -> g_Shi/g_Slo
// EPI 1: T = acc + bias[row]        -> g_T (f32, ld 2304)
// EPI 2: Y = acc                    -> outY (f32, ld 256)
// ---------------------------------------------------------------------------
template <int EPI>
__global__ void __launch_bounds__(256, 1)
mm_bf16(const __nv_bfloat16* __restrict__ Ah, const __nv_bfloat16* __restrict__ Al,
        const __nv_bfloat16* __restrict__ Bh, const __nv_bfloat16* __restrict__ Bl,
        int lda, int ldb, size_t bA, size_t bB, int K,
        const float* __restrict__ bias, float* __restrict__ outY)
{
    extern __shared__ char smv[];
    const uint32_t sb = s2u(smv);
    const int tid = threadIdx.x;
    const int bz = blockIdx.z;
    const int m0 = blockIdx.y * 128, n0 = blockIdx.x * 256;
    const int w = tid >> 5, l = tid & 31;
    const int wm = w >> 2, wn = w & 3;       // 2 x 4 warps, warp tile 64x64

    // loader constants: A row per 2 threads (2 x 16B chunks each), B row per thread (4 chunks)
    const int ar = tid >> 1, ac = tid & 1;
    const int br = tid;
    const __nv_bfloat16* pAh = Ah + (size_t)bz * bA + (size_t)(m0 + ar) * lda + ac * 16;
    const __nv_bfloat16* pAl = Al + (size_t)bz * bA + (size_t)(m0 + ar) * lda + ac * 16;
    const __nv_bfloat16* pBh = Bh + (size_t)bz * bB + (size_t)(n0 + br) * ldb;
    const __nv_bfloat16* pBl = Bl + (size_t)bz * bB + (size_t)(n0 + br) * ldb;
    const uint32_t dA = sb + ar * 80 + ac * 32;
    const uint32_t dB = sb + 20480 + br * 80;

    // fragment lane addressing
    const int sub = l >> 3;
    const uint32_t aOff = (uint32_t)((wm * 64 + (sub & 1) * 8 + (l & 7)) * 80 + (sub >> 1) * 16);
    const uint32_t bOff = (uint32_t)(20480 + (wn * 64 + (l >> 4) * 8 + (l & 7)) * 80 + ((l >> 3) & 1) * 16);

    float acc[4][8][4];
#pragma unroll
    for (int i = 0; i < 4; i++)
#pragma unroll
        for (int j = 0; j < 8; j++)
#pragma unroll
            for (int q = 0; q < 4; q++) acc[i][j][q] = 0.f;

#define LOAD_STAGE(kc, slot) do { \
        const uint32_t so = (uint32_t)(slot) * STG_B; \
        const int ko = (kc) * 32; \
        cp16(dA + so,          pAh + ko); \
        cp16(dA + so + 16,     pAh + ko + 8); \
        cp16(dA + so + 10240,  pAl + ko); \
        cp16(dA + so + 10256,  pAl + ko + 8); \
        cp16(dB + so,          pBh + ko); \
        cp16(dB + so + 16,     pBh + ko + 8); \
        cp16(dB + so + 32,     pBh + ko + 16); \
        cp16(dB + so + 48,     pBh + ko + 24); \
        cp16(dB + so + 20480,  pBl + ko); \
        cp16(dB + so + 20496,  pBl + ko + 8); \
        cp16(dB + so + 20512,  pBl + ko + 16); \
        cp16(dB + so + 20528,  pBl + ko + 24); \
        asm volatile("cp.async.commit_group;"); \
    } while (0)

    const int KN = K / 32;
    LOAD_STAGE(0, 0);
    LOAD_STAGE(1, 1);

    int slot = 0;
    for (int kc = 0; kc < KN; kc++) {
        asm volatile("cp.async.wait_group 1;");
        __syncthreads();
        if (kc + 2 < KN) LOAD_STAGE(kc + 2, (kc + 2) % NST);
        const uint32_t s0 = sb + slot * STG_B;
        slot++; if (slot == NST) slot = 0;
#pragma unroll
        for (int ks = 0; ks < 2; ks++) {
            const uint32_t b0a = s0 + bOff + ks * 32;
            // B fragments: 4 pairs (n16 each) x hi/lo
            uint32_t bfh[8][2], bfl[8][2];
#pragma unroll
            for (int p = 0; p < 4; p++) {
                uint32_t t4[4];
                LDM4(t4, b0a + p * 1280);
                bfh[2 * p][0] = t4[0]; bfh[2 * p][1] = t4[1];
                bfh[2 * p + 1][0] = t4[2]; bfh[2 * p + 1][1] = t4[3];
                LDM4(t4, b0a + p * 1280 + 20480);
                bfl[2 * p][0] = t4[0]; bfl[2 * p][1] = t4[1];
                bfl[2 * p + 1][0] = t4[2]; bfl[2 * p + 1][1] = t4[3];
            }
            const uint32_t a0a = s0 + aOff + ks * 32;
#pragma unroll
            for (int i = 0; i < 4; i++) {
                uint32_t ah[4], al4[4];
                LDM4(ah,  a0a + i * 1280);
                LDM4(al4, a0a + i * 1280 + 10240);
#pragma unroll
                for (int j = 0; j < 8; j++) {
                    MMA16816(acc[i][j], ah[0], ah[1], ah[2], ah[3], bfh[j][0], bfh[j][1]);
                    MMA16816(acc[i][j], ah[0], ah[1], ah[2], ah[3], bfl[j][0], bfl[j][1]);
                    MMA16816(acc[i][j], al4[0], al4[1], al4[2], al4[3], bfh[j][0], bfh[j][1]);
                }
            }
        }
    }

    // epilogue
    float inv = 0.f;
    if (EPI == 0) inv = g_inv[bz];
    const int quad = l >> 2, tq = l & 3;
#pragma unroll
    for (int i = 0; i < 4; i++) {
#pragma unroll
        for (int half = 0; half < 2; half++) {
            const int r = m0 + wm * 64 + i * 16 + quad + half * 8;
            float bvv = 0.f;
            if (EPI == 1) bvv = bias[r];
#pragma unroll
            for (int j = 0; j < 8; j++) {
                const int col = n0 + wn * 64 + j * 8 + tq * 2;
                float v0 = acc[i][j][half * 2 + 0];
                float v1 = acc[i][j][half * 2 + 1];
                if (EPI == 0) {
                    v0 = fmaxf(v0 * inv, 0.f); v0 *= v0;
                    v1 = fmaxf(v1 * inv, 0.f); v1 *= v1;
                    __nv_bfloat16 h0 = __float2bfloat16(v0), h1 = __float2bfloat16(v1);
                    uint32_t hp = (uint32_t)__bfloat16_as_ushort(h0) | ((uint32_t)__bfloat16_as_ushort(h1) << 16);
                    uint32_t lp = packbf(v0 - __bfloat162float(h0), v1 - __bfloat162float(h1));
                    size_t base = (size_t)bz * HWDIM * HWDIM + (size_t)r * HWDIM + col;
                    *(uint32_t*)(g_Shi + base) = hp;
                    *(uint32_t*)(g_Slo + base) = lp;
                } else if (EPI == 1) {
                    float2 vv; vv.x = v0 + bvv; vv.y = v1 + bvv;
                    *(float2*)(g_T + (size_t)bz * PB + (size_t)r * HWDIM + col) = vv;
                } else {
                    float2 vv; vv.x = v0; vv.y = v1;
                    *(float2*)(outY + (size_t)bz * PB + (size_t)r * CDIM + col) = vv;
                }
            }
        }
    }
#undef LOAD_STAGE
}

// ---------------------------------------------------------------------------
// Host launch
// ---------------------------------------------------------------------------
extern "C" void kernel_launch(void* const* d_in, const int* in_sizes, int n_in,
                              void* d_out, int out_size)
{
    const float* x    = (const float*)d_in[0];
    const float* W    = (const float*)d_in[1];
    const float* bias = (const float*)d_in[2];
    float* out        = (float*)d_out;

    void *pXhi, *pXlo, *pXThi, *pXTlo, *pWhi, *pWlo, *pShi, *pSlo, *pTThi, *pTTlo, *pT;
    cudaGetSymbolAddress(&pXhi,  g_Xhi);
    cudaGetSymbolAddress(&pXlo,  g_Xlo);
    cudaGetSymbolAddress(&pXThi, g_XThi);
    cudaGetSymbolAddress(&pXTlo, g_XTlo);
    cudaGetSymbolAddress(&pWhi,  g_Whi);
    cudaGetSymbolAddress(&pWlo,  g_Wlo);
    cudaGetSymbolAddress(&pShi,  g_Shi);
    cudaGetSymbolAddress(&pSlo,  g_Slo);
    cudaGetSymbolAddress(&pTThi, g_TThi);
    cudaGetSymbolAddress(&pTTlo, g_TTlo);
    cudaGetSymbolAddress(&pT,    g_T);

    static bool attr_done = false;
    if (!attr_done) {
        cudaFuncSetAttribute(mm_bf16<0>, cudaFuncAttributeMaxDynamicSharedMemorySize, SMEM_B);
        cudaFuncSetAttribute(mm_bf16<1>, cudaFuncAttributeMaxDynamicSharedMemorySize, SMEM_B);
        cudaFuncSetAttribute(mm_bf16<2>, cudaFuncAttributeMaxDynamicSharedMemorySize, SMEM_B);
        attr_done = true;
    }

    // 1) norm
    sumsq_kernel<<<BATCH, 512>>>(x);

    // 2) splits
    split_flat<<<(BATCH * PB / 4 + 255) / 256, 256>>>((const float4*)x, (uint2*)pXhi, (uint2*)pXlo, BATCH * PB / 4);
    split_flat<<<(CDIM * CDIM / 4 + 255) / 256, 256>>>((const float4*)W, (uint2*)pWhi, (uint2*)pWlo, CDIM * CDIM / 4);
    {   // XT = transpose(x viewed [256,2304]) -> [2304,256]
        dim3 g(HWDIM / 32, CDIM / 32, BATCH);
        transpose_split<<<g, dim3(32, 8)>>>(x, (__nv_bfloat16*)pXThi, (__nv_bfloat16*)pXTlo, CDIM, HWDIM);
    }

    // 3) GEMM2: T[o,p] = W @ x2 + bias      (M=256, N=2304, K=256)
    mm_bf16<1><<<dim3(HWDIM / 256, CDIM / 128, BATCH), 256, SMEM_B>>>(
        (const __nv_bfloat16*)pWhi, (const __nv_bfloat16*)pWlo,
        (const __nv_bfloat16*)pXThi, (const __nv_bfloat16*)pXTlo,
        CDIM, CDIM, 0, (size_t)PB, CDIM, bias, nullptr);

    // 4) TT = transpose(T viewed [2304,256]) -> [256,2304]
    {
        dim3 g(CDIM / 32, HWDIM / 32, BATCH);
        transpose_split<<<g, dim3(32, 8)>>>((const float*)pT,
            (__nv_bfloat16*)pTThi, (__nv_bfloat16*)pTTlo, HWDIM, CDIM);
    }

    // 5) GEMM1: S = relu((x1 @ x2) * inv)^2   (M=N=2304, K=256)
    mm_bf16<0><<<dim3(HWDIM / 256, HWDIM / 128, BATCH), 256, SMEM_B>>>(
        (const __nv_bfloat16*)pXhi, (const __nv_bfloat16*)pXlo,
        (const __nv_bfloat16*)pXThi, (const __nv_bfloat16*)pXTlo,
        CDIM, CDIM, (size_t)PB, (size_t)PB, CDIM, nullptr, nullptr);

    // 6) GEMM3: Y = S @ Tview -> out          (M=2304, N=256, K=2304)
    mm_bf16<2><<<dim3(CDIM / 256, HWDIM / 128, BATCH), 256, SMEM_B>>>(
        (const __nv_bfloat16*)pShi, (const __nv_bfloat16*)pSlo,
        (const __nv_bfloat16*)pTThi, (const __nv_bfloat16*)pTTlo,
        HWDIM, HWDIM, (size_t)HWDIM * HWDIM, (size_t)PB, HWDIM, nullptr, out);
}

// round 9
// speedup vs baseline: 1.4689x; 1.4689x over previous
#include <cuda_runtime.h>
#include <cuda_fp16.h>
#include <cstdint>

#define BATCH 16
#define CDIM 256
#define HWDIM 2304
#define PB (CDIM * HWDIM)

#define NST 3
#define STG3 40960u                 // Ahi+Alo+Bhi+Blo, 128 rows x 80B each
#define STG1 20480u                 // Ahi+Bhi
#define SMEM3 (NST * STG3)          // 122880
#define SMEM1 (NST * STG1)          // 61440

// ---------------------------------------------------------------------------
// Device scratch (allocation-free)
// ---------------------------------------------------------------------------
__device__ float g_inv[BATCH];
__device__ float g_T[(size_t)BATCH * PB];
__device__ __align__(1024) __half g_Xhi[(size_t)BATCH * PB];
__device__ __align__(1024) __half g_Xlo[(size_t)BATCH * PB];
__device__ __align__(1024) __half g_XThi[(size_t)BATCH * PB];
__device__ __align__(1024) __half g_XTlo[(size_t)BATCH * PB];
__device__ __align__(1024) __half g_Whi[CDIM * CDIM];
__device__ __align__(1024) __half g_Wlo[CDIM * CDIM];
__device__ __align__(1024) __half g_Shat[(size_t)BATCH * HWDIM * HWDIM];  // 170MB, scaled S
__device__ __align__(1024) __half g_TThi[(size_t)BATCH * PB];

// ---------------------------------------------------------------------------
// per-batch 1/||x||^2
// ---------------------------------------------------------------------------
__global__ void sumsq_kernel(const float* __restrict__ x) {
    const int b = blockIdx.x;
    const float4* p = (const float4*)(x + (size_t)b * PB);
    float s = 0.f;
    for (int i = threadIdx.x; i < PB / 4; i += blockDim.x) {
        float4 v = p[i];
        s += v.x * v.x + v.y * v.y + v.z * v.z + v.w * v.w;
    }
    __shared__ float red[512];
    red[threadIdx.x] = s;
    __syncthreads();
    for (int off = blockDim.x >> 1; off > 0; off >>= 1) {
        if (threadIdx.x < (unsigned)off) red[threadIdx.x] += red[threadIdx.x + off];
        __syncthreads();
    }
    if (threadIdx.x == 0) g_inv[b] = 1.0f / red[0];
}

// ---------------------------------------------------------------------------
// fp16 helpers
// ---------------------------------------------------------------------------
__device__ __forceinline__ uint32_t packhf(float a, float b) {
    __half ha = __float2half_rn(a), hb = __float2half_rn(b);
    return (uint32_t)__half_as_ushort(ha) | ((uint32_t)__half_as_ushort(hb) << 16);
}

// f32 -> fp16 hi/lo split (flat)
__global__ void split_flat(const float4* __restrict__ in,
                           uint2* __restrict__ hi, uint2* __restrict__ lo, int n4) {
    int i = blockIdx.x * blockDim.x + threadIdx.x;
    if (i >= n4) return;
    float4 v = in[i];
    __half h0 = __float2half_rn(v.x), h1 = __float2half_rn(v.y);
    __half h2 = __float2half_rn(v.z), h3 = __float2half_rn(v.w);
    uint2 hp, lp;
    hp.x = (uint32_t)__half_as_ushort(h0) | ((uint32_t)__half_as_ushort(h1) << 16);
    hp.y = (uint32_t)__half_as_ushort(h2) | ((uint32_t)__half_as_ushort(h3) << 16);
    lp.x = packhf(v.x - __half2float(h0), v.y - __half2float(h1));
    lp.y = packhf(v.z - __half2float(h2), v.w - __half2float(h3));
    hi[i] = hp;
    lo[i] = lp;
}

// per-batch transpose + fp16 hi/lo split: [rows,cols] f32 -> [cols,rows]
__global__ void transpose_split(const float* __restrict__ in,
                                __half* __restrict__ hi, __half* __restrict__ lo,
                                int rows, int cols) {
    __shared__ float t[32][33];
    const size_t off = (size_t)blockIdx.z * rows * cols;
    const int c0 = blockIdx.x * 32, r0 = blockIdx.y * 32;
    const int x = threadIdx.x, y0 = threadIdx.y;
#pragma unroll
    for (int yy = y0; yy < 32; yy += 8)
        t[yy][x] = in[off + (size_t)(r0 + yy) * cols + c0 + x];
    __syncthreads();
#pragma unroll
    for (int yy = y0; yy < 32; yy += 8) {
        float v = t[x][yy];
        __half h = __float2half_rn(v);
        size_t o = off + (size_t)(c0 + yy) * rows + r0 + x;
        hi[o] = h;
        lo[o] = __float2half_rn(v - __half2float(h));
    }
}

// per-batch transpose + fp16 cast (hi only)
__global__ void transpose_cast(const float* __restrict__ in,
                               __half* __restrict__ hi, int rows, int cols) {
    __shared__ float t[32][33];
    const size_t off = (size_t)blockIdx.z * rows * cols;
    const int c0 = blockIdx.x * 32, r0 = blockIdx.y * 32;
    const int x = threadIdx.x, y0 = threadIdx.y;
#pragma unroll
    for (int yy = y0; yy < 32; yy += 8)
        t[yy][x] = in[off + (size_t)(r0 + yy) * cols + c0 + x];
    __syncthreads();
#pragma unroll
    for (int yy = y0; yy < 32; yy += 8)
        hi[off + (size_t)(c0 + yy) * rows + r0 + x] = __float2half_rn(t[x][yy]);
}

// ---------------------------------------------------------------------------
// PTX helpers (sm_80 baseline — compiles on plain compute_103)
// ---------------------------------------------------------------------------
__device__ __forceinline__ uint32_t s2u(const void* p) {
    uint32_t a;
    asm("{ .reg .u64 t; cvta.to.shared.u64 t, %1; cvt.u32.u64 %0, t; }" : "=r"(a) : "l"(p));
    return a;
}
__device__ __forceinline__ void cp16(uint32_t d, const void* g) {
    asm volatile("cp.async.cg.shared.global [%0], [%1], 16;" :: "r"(d), "l"(g));
}
#define LDM4(r, addr) \
    asm volatile("ldmatrix.sync.aligned.m8n8.x4.shared.b16 {%0,%1,%2,%3}, [%4];" \
        : "=r"((r)[0]), "=r"((r)[1]), "=r"((r)[2]), "=r"((r)[3]) : "r"(addr))
#define MMAH(c, a0, a1, a2, a3, b0, b1) \
    asm volatile("mma.sync.aligned.m16n8k16.row.col.f32.f16.f16.f32 " \
        "{%0,%1,%2,%3}, {%4,%5,%6,%7}, {%8,%9}, {%0,%1,%2,%3};" \
        : "+f"((c)[0]), "+f"((c)[1]), "+f"((c)[2]), "+f"((c)[3]) \
        : "r"(a0), "r"(a1), "r"(a2), "r"(a3), "r"(b0), "r"(b1))

// ---------------------------------------------------------------------------
// fp16 mma.sync GEMM, CTA 128x128, warp tile 64x32, KC=32
//   D[m,n] = sum_k A[m,k]*B[n,k]   (K-major fp16)
// TERMS=3: ahi*bhi + ahi*blo + alo*bhi   (fp32-faithful to ~2^-22)
// TERMS=1: ahi*bhi only
// Stage layout (80B row stride): Ahi@0, [Alo@10240,] Bhi@(TERMS==3?20480:10240), [Blo@30720]
// EPI 0: Shat = relu(acc/256)^2 -> g_Shat (fp16)
// EPI 1: T = acc + bias[row]     -> g_T (f32, ld 2304)
// EPI 2: Y = acc * inv^2*65536   -> outY (f32, ld 256)
// ---------------------------------------------------------------------------
template <int EPI, int TERMS>
__global__ void __launch_bounds__(256, (TERMS == 1) ? 2 : 1)
mm_fp16(const __half* __restrict__ Ah, const __half* __restrict__ Al,
        const __half* __restrict__ Bh, const __half* __restrict__ Bl,
        int lda, int ldb, size_t bA, size_t bB, int K,
        const float* __restrict__ bias, float* __restrict__ outY)
{
    constexpr uint32_t STG = (TERMS == 3) ? STG3 : STG1;
    constexpr uint32_t oBh = (TERMS == 3) ? 20480u : 10240u;

    extern __shared__ char smv[];
    const uint32_t sb = s2u(smv);
    const int tid = threadIdx.x;
    const int bz = blockIdx.z;
    const int m0 = blockIdx.y * 128, n0 = blockIdx.x * 128;
    const int w = tid >> 5, l = tid & 31;
    const int wm = w >> 2, wn = w & 3;       // 2 x 4 warps, warp tile 64x32

    // loader: row = tid>>1 (128 rows), 32B chunk = (tid&1) within the 64B row
    const int r = tid >> 1, c = tid & 1;
    const __half* pAh = Ah + (size_t)bz * bA + (size_t)(m0 + r) * lda + c * 16;
    const __half* pAl = (TERMS == 3) ? (Al + (size_t)bz * bA + (size_t)(m0 + r) * lda + c * 16) : nullptr;
    const __half* pBh = Bh + (size_t)bz * bB + (size_t)(n0 + r) * ldb + c * 16;
    const __half* pBl = (TERMS == 3) ? (Bl + (size_t)bz * bB + (size_t)(n0 + r) * ldb + c * 16) : nullptr;
    const uint32_t dA = sb + r * 80 + c * 32;
    const uint32_t dB = sb + oBh + r * 80 + c * 32;

    // fragment lane addressing (R6-verified scheme, 80B stride)
    const int sub = l >> 3;
    const uint32_t aOff = (uint32_t)((wm * 64 + (sub & 1) * 8 + (l & 7)) * 80 + (sub >> 1) * 16);
    const uint32_t bOff = (uint32_t)(oBh + (wn * 32 + (l >> 4) * 8 + (l & 7)) * 80 + ((l >> 3) & 1) * 16);

    float acc[4][4][4];
#pragma unroll
    for (int i = 0; i < 4; i++)
#pragma unroll
        for (int j = 0; j < 4; j++)
#pragma unroll
            for (int q = 0; q < 4; q++) acc[i][j][q] = 0.f;

#define LOAD_STAGE(kc, slot) do { \
        const uint32_t so = (uint32_t)(slot) * STG; \
        const int ko = (kc) * 32; \
        cp16(dA + so,      pAh + ko); \
        cp16(dA + so + 16, pAh + ko + 8); \
        cp16(dB + so,      pBh + ko); \
        cp16(dB + so + 16, pBh + ko + 8); \
        if (TERMS == 3) { \
            cp16(dA + so + 10240, pAl + ko); \
            cp16(dA + so + 10256, pAl + ko + 8); \
            cp16(dB + so + 10240, pBl + ko); \
            cp16(dB + so + 10256, pBl + ko + 8); \
        } \
        asm volatile("cp.async.commit_group;"); \
    } while (0)

    const int KN = K / 32;
    LOAD_STAGE(0, 0);
    LOAD_STAGE(1, 1);

    int slot = 0;
    for (int kc = 0; kc < KN; kc++) {
        asm volatile("cp.async.wait_group 1;");
        __syncthreads();
        if (kc + 2 < KN) LOAD_STAGE(kc + 2, (kc + 2) % NST);
        const uint32_t s0 = sb + slot * STG;
        slot++; if (slot == NST) slot = 0;
#pragma unroll
        for (int ks = 0; ks < 2; ks++) {
            // B fragments: 2 LDM4 -> 4 n8 tiles (hi); optionally lo
            uint32_t bfh[4][2], bfl[4][2];
            const uint32_t b0a = s0 + bOff + ks * 32;
#pragma unroll
            for (int p = 0; p < 2; p++) {
                uint32_t t4[4];
                LDM4(t4, b0a + p * (16 * 80));
                bfh[2 * p][0] = t4[0]; bfh[2 * p][1] = t4[1];
                bfh[2 * p + 1][0] = t4[2]; bfh[2 * p + 1][1] = t4[3];
                if (TERMS == 3) {
                    LDM4(t4, b0a + p * (16 * 80) + 10240);
                    bfl[2 * p][0] = t4[0]; bfl[2 * p][1] = t4[1];
                    bfl[2 * p + 1][0] = t4[2]; bfl[2 * p + 1][1] = t4[3];
                }
            }
            const uint32_t a0a = s0 + aOff + ks * 32;
#pragma unroll
            for (int i = 0; i < 4; i++) {
                uint32_t ah[4];
                LDM4(ah, a0a + i * 1280);
                if (TERMS == 3) {
                    uint32_t al4[4];
                    LDM4(al4, a0a + i * 1280 + 10240);
#pragma unroll
                    for (int j = 0; j < 4; j++) {
                        MMAH(acc[i][j], ah[0], ah[1], ah[2], ah[3], bfh[j][0], bfh[j][1]);
                        MMAH(acc[i][j], ah[0], ah[1], ah[2], ah[3], bfl[j][0], bfl[j][1]);
                        MMAH(acc[i][j], al4[0], al4[1], al4[2], al4[3], bfh[j][0], bfh[j][1]);
                    }
                } else {
#pragma unroll
                    for (int j = 0; j < 4; j++)
                        MMAH(acc[i][j], ah[0], ah[1], ah[2], ah[3], bfh[j][0], bfh[j][1]);
                }
            }
        }
    }

    // epilogue
    float factor = 0.f;
    if (EPI == 2) {
        float inv = g_inv[bz];
        factor = inv * inv * 65536.f;
    }
    const int quad = l >> 2, tq = l & 3;
#pragma unroll
    for (int i = 0; i < 4; i++) {
#pragma unroll
        for (int half = 0; half < 2; half++) {
            const int rr = m0 + wm * 64 + i * 16 + quad + half * 8;
            float bvv = 0.f;
            if (EPI == 1) bvv = bias[rr];
#pragma unroll
            for (int j = 0; j < 4; j++) {
                const int col = n0 + wn * 32 + j * 8 + tq * 2;
                float v0 = acc[i][j][half * 2 + 0];
                float v1 = acc[i][j][half * 2 + 1];
                if (EPI == 0) {
                    // Shat = relu(acc/256)^2  (fp16-range-safe scaled S)
                    v0 = fmaxf(v0 * 0.00390625f, 0.f); v0 *= v0;
                    v1 = fmaxf(v1 * 0.00390625f, 0.f); v1 *= v1;
                    size_t base = (size_t)bz * HWDIM * HWDIM + (size_t)rr * HWDIM + col;
                    *(uint32_t*)(g_Shat + base) = packhf(v0, v1);
                } else if (EPI == 1) {
                    float2 vv; vv.x = v0 + bvv; vv.y = v1 + bvv;
                    *(float2*)(g_T + (size_t)bz * PB + (size_t)rr * HWDIM + col) = vv;
                } else {
                    float2 vv; vv.x = v0 * factor; vv.y = v1 * factor;
                    *(float2*)(outY + (size_t)bz * PB + (size_t)rr * CDIM + col) = vv;
                }
            }
        }
    }
#undef LOAD_STAGE
}

// ---------------------------------------------------------------------------
// Host launch
// ---------------------------------------------------------------------------
extern "C" void kernel_launch(void* const* d_in, const int* in_sizes, int n_in,
                              void* d_out, int out_size)
{
    const float* x    = (const float*)d_in[0];
    const float* W    = (const float*)d_in[1];
    const float* bias = (const float*)d_in[2];
    float* out        = (float*)d_out;

    void *pXhi, *pXlo, *pXThi, *pXTlo, *pWhi, *pWlo, *pShat, *pTThi, *pT;
    cudaGetSymbolAddress(&pXhi,  g_Xhi);
    cudaGetSymbolAddress(&pXlo,  g_Xlo);
    cudaGetSymbolAddress(&pXThi, g_XThi);
    cudaGetSymbolAddress(&pXTlo, g_XTlo);
    cudaGetSymbolAddress(&pWhi,  g_Whi);
    cudaGetSymbolAddress(&pWlo,  g_Wlo);
    cudaGetSymbolAddress(&pShat, g_Shat);
    cudaGetSymbolAddress(&pTThi, g_TThi);
    cudaGetSymbolAddress(&pT,    g_T);

    static bool attr_done = false;
    if (!attr_done) {
        cudaFuncSetAttribute(mm_fp16<0, 3>, cudaFuncAttributeMaxDynamicSharedMemorySize, SMEM3);
        cudaFuncSetAttribute(mm_fp16<1, 3>, cudaFuncAttributeMaxDynamicSharedMemorySize, SMEM3);
        cudaFuncSetAttribute(mm_fp16<2, 1>, cudaFuncAttributeMaxDynamicSharedMemorySize, SMEM1);
        attr_done = true;
    }

    // 1) norm
    sumsq_kernel<<<BATCH, 512>>>(x);

    // 2) splits + transposes
    split_flat<<<(BATCH * PB / 4 + 255) / 256, 256>>>((const float4*)x, (uint2*)pXhi, (uint2*)pXlo, BATCH * PB / 4);
    split_flat<<<(CDIM * CDIM / 4 + 255) / 256, 256>>>((const float4*)W, (uint2*)pWhi, (uint2*)pWlo, CDIM * CDIM / 4);
    {   // XT = transpose(x viewed [256,2304]) -> [2304,256] fp16 hi/lo
        dim3 g(HWDIM / 32, CDIM / 32, BATCH);
        transpose_split<<<g, dim3(32, 8)>>>(x, (__half*)pXThi, (__half*)pXTlo, CDIM, HWDIM);
    }

    // 3) GEMM2 (3-term): T[o,p] = W @ x2 + bias   (M=256, N=2304, K=256)
    mm_fp16<1, 3><<<dim3(HWDIM / 128, CDIM / 128, BATCH), 256, SMEM3>>>(
        (const __half*)pWhi, (const __half*)pWlo,
        (const __half*)pXThi, (const __half*)pXTlo,
        CDIM, CDIM, 0, (size_t)PB, CDIM, bias, nullptr);

    // 4) TT = transpose(T viewed [2304,256]) -> [256,2304] fp16
    {
        dim3 g(CDIM / 32, HWDIM / 32, BATCH);
        transpose_cast<<<g, dim3(32, 8)>>>((const float*)pT, (__half*)pTThi, HWDIM, CDIM);
    }

    // 5) GEMM1 (3-term): Shat = relu((x1 @ x2)/256)^2   (M=N=2304, K=256)
    mm_fp16<0, 3><<<dim3(HWDIM / 128, HWDIM / 128, BATCH), 256, SMEM3>>>(
        (const __half*)pXhi, (const __half*)pXlo,
        (const __half*)pXThi, (const __half*)pXTlo,
        CDIM, CDIM, (size_t)PB, (size_t)PB, CDIM, nullptr, nullptr);

    // 6) GEMM3 (1-term): Y = Shat @ Tview * inv^2*2^16 -> out  (M=2304, N=256, K=2304)
    mm_fp16<2, 1><<<dim3(CDIM / 128, HWDIM / 128, BATCH), 256, SMEM1>>>(
        (const __half*)pShat, nullptr, (const __half*)pTThi, nullptr,
        HWDIM, HWDIM, (size_t)HWDIM * HWDIM, (size_t)PB, HWDIM, nullptr, out);
}

// round 10
// speedup vs baseline: 1.9260x; 1.3112x over previous
#include <cuda_runtime.h>
#include <cuda_fp16.h>
#include <cstdint>

#define BATCH 16
#define CDIM 256
#define HWDIM 2304
#define PB (CDIM * HWDIM)

#define NST 3
#define STG3 40960u                 // Ahi+Alo+Bhi+Blo, 128 rows x 80B each
#define STG2 30720u                 // Ahi+Alo+Bhi
#define STG1 20480u                 // Ahi+Bhi
#define SMEM3 (NST * STG3)          // 122880
#define SMEM2 (NST * STG2)          // 92160
#define SMEM1 (NST * STG1)          // 61440

// ---------------------------------------------------------------------------
// Device scratch (allocation-free)
// ---------------------------------------------------------------------------
__device__ float g_inv[BATCH];
__device__ float g_T[(size_t)BATCH * PB];
__device__ __align__(1024) __half g_Xhi[(size_t)BATCH * PB];
__device__ __align__(1024) __half g_Xlo[(size_t)BATCH * PB];
__device__ __align__(1024) __half g_XThi[(size_t)BATCH * PB];
__device__ __align__(1024) __half g_XTlo[(size_t)BATCH * PB];
__device__ __align__(1024) __half g_Whi[CDIM * CDIM];
__device__ __align__(1024) __half g_Wlo[CDIM * CDIM];
__device__ __align__(1024) __half g_Shat[(size_t)BATCH * HWDIM * HWDIM];  // 170MB, scaled S
__device__ __align__(1024) __half g_TThi[(size_t)BATCH * PB];

// ---------------------------------------------------------------------------
// per-batch 1/||x||^2
// ---------------------------------------------------------------------------
__global__ void sumsq_kernel(const float* __restrict__ x) {
    const int b = blockIdx.x;
    const float4* p = (const float4*)(x + (size_t)b * PB);
    float s = 0.f;
    for (int i = threadIdx.x; i < PB / 4; i += blockDim.x) {
        float4 v = p[i];
        s += v.x * v.x + v.y * v.y + v.z * v.z + v.w * v.w;
    }
    __shared__ float red[512];
    red[threadIdx.x] = s;
    __syncthreads();
    for (int off = blockDim.x >> 1; off > 0; off >>= 1) {
        if (threadIdx.x < (unsigned)off) red[threadIdx.x] += red[threadIdx.x + off];
        __syncthreads();
    }
    if (threadIdx.x == 0) g_inv[b] = 1.0f / red[0];
}

// ---------------------------------------------------------------------------
// fp16 helpers
// ---------------------------------------------------------------------------
__device__ __forceinline__ uint32_t packhf(float a, float b) {
    __half ha = __float2half_rn(a), hb = __float2half_rn(b);
    return (uint32_t)__half_as_ushort(ha) | ((uint32_t)__half_as_ushort(hb) << 16);
}

// f32 -> fp16 hi/lo split (flat)
__global__ void split_flat(const float4* __restrict__ in,
                           uint2* __restrict__ hi, uint2* __restrict__ lo, int n4) {
    int i = blockIdx.x * blockDim.x + threadIdx.x;
    if (i >= n4) return;
    float4 v = in[i];
    __half h0 = __float2half_rn(v.x), h1 = __float2half_rn(v.y);
    __half h2 = __float2half_rn(v.z), h3 = __float2half_rn(v.w);
    uint2 hp, lp;
    hp.x = (uint32_t)__half_as_ushort(h0) | ((uint32_t)__half_as_ushort(h1) << 16);
    hp.y = (uint32_t)__half_as_ushort(h2) | ((uint32_t)__half_as_ushort(h3) << 16);
    lp.x = packhf(v.x - __half2float(h0), v.y - __half2float(h1));
    lp.y = packhf(v.z - __half2float(h2), v.w - __half2float(h3));
    hi[i] = hp;
    lo[i] = lp;
}

// per-batch transpose + fp16 hi/lo split: [rows,cols] f32 -> [cols,rows]
__global__ void transpose_split(const float* __restrict__ in,
                                __half* __restrict__ hi, __half* __restrict__ lo,
                                int rows, int cols) {
    __shared__ float t[32][33];
    const size_t off = (size_t)blockIdx.z * rows * cols;
    const int c0 = blockIdx.x * 32, r0 = blockIdx.y * 32;
    const int x = threadIdx.x, y0 = threadIdx.y;
#pragma unroll
    for (int yy = y0; yy < 32; yy += 8)
        t[yy][x] = in[off + (size_t)(r0 + yy) * cols + c0 + x];
    __syncthreads();
#pragma unroll
    for (int yy = y0; yy < 32; yy += 8) {
        float v = t[x][yy];
        __half h = __float2half_rn(v);
        size_t o = off + (size_t)(c0 + yy) * rows + r0 + x;
        hi[o] = h;
        lo[o] = __float2half_rn(v - __half2float(h));
    }
}

// per-batch transpose + fp16 cast (hi only)
__global__ void transpose_cast(const float* __restrict__ in,
                               __half* __restrict__ hi, int rows, int cols) {
    __shared__ float t[32][33];
    const size_t off = (size_t)blockIdx.z * rows * cols;
    const int c0 = blockIdx.x * 32, r0 = blockIdx.y * 32;
    const int x = threadIdx.x, y0 = threadIdx.y;
#pragma unroll
    for (int yy = y0; yy < 32; yy += 8)
        t[yy][x] = in[off + (size_t)(r0 + yy) * cols + c0 + x];
    __syncthreads();
#pragma unroll
    for (int yy = y0; yy < 32; yy += 8)
        hi[off + (size_t)(c0 + yy) * rows + r0 + x] = __float2half_rn(t[x][yy]);
}

// ---------------------------------------------------------------------------
// PTX helpers (sm_80 baseline — compiles on plain compute_103)
// ---------------------------------------------------------------------------
__device__ __forceinline__ uint32_t s2u(const void* p) {
    uint32_t a;
    asm("{ .reg .u64 t; cvta.to.shared.u64 t, %1; cvt.u32.u64 %0, t; }" : "=r"(a) : "l"(p));
    return a;
}
__device__ __forceinline__ void cp16(uint32_t d, const void* g) {
    asm volatile("cp.async.cg.shared.global [%0], [%1], 16;" :: "r"(d), "l"(g));
}
#define LDM4(r, addr) \
    asm volatile("ldmatrix.sync.aligned.m8n8.x4.shared.b16 {%0,%1,%2,%3}, [%4];" \
        : "=r"((r)[0]), "=r"((r)[1]), "=r"((r)[2]), "=r"((r)[3]) : "r"(addr))
#define MMAH(c, a0, a1, a2, a3, b0, b1) \
    asm volatile("mma.sync.aligned.m16n8k16.row.col.f32.f16.f16.f32 " \
        "{%0,%1,%2,%3}, {%4,%5,%6,%7}, {%8,%9}, {%0,%1,%2,%3};" \
        : "+f"((c)[0]), "+f"((c)[1]), "+f"((c)[2]), "+f"((c)[3]) \
        : "r"(a0), "r"(a1), "r"(a2), "r"(a3), "r"(b0), "r"(b1))

// ---------------------------------------------------------------------------
// fp16 mma.sync GEMM, CTA 128x128, warp tile 64x32, KC=32
//   D[m,n] = sum_k A[m,k]*B[n,k]   (K-major fp16)
// TERMS=3: ahi*bhi + ahi*blo + alo*bhi   (~2^-22 residual)
// TERMS=2: ahi*bhi + alo*bhi = A*Bhi     (~2^-12 residual on B only)
// TERMS=1: ahi*bhi
// Stage layout (80B row stride): Ahi@0, [Alo@10240,] Bhi@oBh, [Blo@oBh+10240]
// EPI 0: Shat = relu(acc/256)^2 -> g_Shat (fp16)
// EPI 1: T = acc + bias[row]     -> g_T (f32, ld 2304)
// EPI 2: Y = acc * inv^2*65536   -> outY (f32, ld 256)
// ---------------------------------------------------------------------------
template <int EPI, int TERMS>
__global__ void __launch_bounds__(256, (TERMS == 3) ? 1 : 2)
mm_fp16(const __half* __restrict__ Ah, const __half* __restrict__ Al,
        const __half* __restrict__ Bh, const __half* __restrict__ Bl,
        int lda, int ldb, size_t bA, size_t bB, int K,
        const float* __restrict__ bias, float* __restrict__ outY)
{
    constexpr uint32_t STG = (TERMS == 3) ? STG3 : ((TERMS == 2) ? STG2 : STG1);
    constexpr uint32_t oBh = (TERMS == 1) ? 10240u : 20480u;

    extern __shared__ char smv[];
    const uint32_t sb = s2u(smv);
    const int tid = threadIdx.x;
    const int bz = blockIdx.z;
    const int m0 = blockIdx.y * 128, n0 = blockIdx.x * 128;
    const int w = tid >> 5, l = tid & 31;
    const int wm = w >> 2, wn = w & 3;       // 2 x 4 warps, warp tile 64x32

    // loader: row = tid>>1 (128 rows), 32B chunk = (tid&1) within the 64B row
    const int r = tid >> 1, c = tid & 1;
    const __half* pAh = Ah + (size_t)bz * bA + (size_t)(m0 + r) * lda + c * 16;
    const __half* pAl = (TERMS >= 2) ? (Al + (size_t)bz * bA + (size_t)(m0 + r) * lda + c * 16) : nullptr;
    const __half* pBh = Bh + (size_t)bz * bB + (size_t)(n0 + r) * ldb + c * 16;
    const __half* pBl = (TERMS == 3) ? (Bl + (size_t)bz * bB + (size_t)(n0 + r) * ldb + c * 16) : nullptr;
    const uint32_t dA = sb + r * 80 + c * 32;
    const uint32_t dB = sb + oBh + r * 80 + c * 32;

    // fragment lane addressing (verified scheme, 80B stride)
    const int sub = l >> 3;
    const uint32_t aOff = (uint32_t)((wm * 64 + (sub & 1) * 8 + (l & 7)) * 80 + (sub >> 1) * 16);
    const uint32_t bOff = (uint32_t)(oBh + (wn * 32 + (l >> 4) * 8 + (l & 7)) * 80 + ((l >> 3) & 1) * 16);

    float acc[4][4][4];
#pragma unroll
    for (int i = 0; i < 4; i++)
#pragma unroll
        for (int j = 0; j < 4; j++)
#pragma unroll
            for (int q = 0; q < 4; q++) acc[i][j][q] = 0.f;

#define LOAD_STAGE(kc, slot) do { \
        const uint32_t so = (uint32_t)(slot) * STG; \
        const int ko = (kc) * 32; \
        cp16(dA + so,      pAh + ko); \
        cp16(dA + so + 16, pAh + ko + 8); \
        cp16(dB + so,      pBh + ko); \
        cp16(dB + so + 16, pBh + ko + 8); \
        if (TERMS >= 2) { \
            cp16(dA + so + 10240, pAl + ko); \
            cp16(dA + so + 10256, pAl + ko + 8); \
        } \
        if (TERMS == 3) { \
            cp16(dB + so + 10240, pBl + ko); \
            cp16(dB + so + 10256, pBl + ko + 8); \
        } \
        asm volatile("cp.async.commit_group;"); \
    } while (0)

    const int KN = K / 32;
    LOAD_STAGE(0, 0);
    LOAD_STAGE(1, 1);

    int slot = 0;
    for (int kc = 0; kc < KN; kc++) {
        asm volatile("cp.async.wait_group 1;");
        __syncthreads();
        if (kc + 2 < KN) LOAD_STAGE(kc + 2, (kc + 2) % NST);
        const uint32_t s0 = sb + slot * STG;
        slot++; if (slot == NST) slot = 0;
#pragma unroll
        for (int ks = 0; ks < 2; ks++) {
            // B fragments: 2 LDM4 -> 4 n8 tiles (hi); optionally lo
            uint32_t bfh[4][2], bfl[4][2];
            const uint32_t b0a = s0 + bOff + ks * 32;
#pragma unroll
            for (int p = 0; p < 2; p++) {
                uint32_t t4[4];
                LDM4(t4, b0a + p * (16 * 80));
                bfh[2 * p][0] = t4[0]; bfh[2 * p][1] = t4[1];
                bfh[2 * p + 1][0] = t4[2]; bfh[2 * p + 1][1] = t4[3];
                if (TERMS == 3) {
                    LDM4(t4, b0a + p * (16 * 80) + 10240);
                    bfl[2 * p][0] = t4[0]; bfl[2 * p][1] = t4[1];
                    bfl[2 * p + 1][0] = t4[2]; bfl[2 * p + 1][1] = t4[3];
                }
            }
            const uint32_t a0a = s0 + aOff + ks * 32;
#pragma unroll
            for (int i = 0; i < 4; i++) {
                uint32_t ah[4];
                LDM4(ah, a0a + i * 1280);
                if (TERMS >= 2) {
                    uint32_t al4[4];
                    LDM4(al4, a0a + i * 1280 + 10240);
#pragma unroll
                    for (int j = 0; j < 4; j++) {
                        MMAH(acc[i][j], ah[0], ah[1], ah[2], ah[3], bfh[j][0], bfh[j][1]);
                        if (TERMS == 3)
                            MMAH(acc[i][j], ah[0], ah[1], ah[2], ah[3], bfl[j][0], bfl[j][1]);
                        MMAH(acc[i][j], al4[0], al4[1], al4[2], al4[3], bfh[j][0], bfh[j][1]);
                    }
                } else {
#pragma unroll
                    for (int j = 0; j < 4; j++)
                        MMAH(acc[i][j], ah[0], ah[1], ah[2], ah[3], bfh[j][0], bfh[j][1]);
                }
            }
        }
    }

    // epilogue
    float factor = 0.f;
    if (EPI == 2) {
        float inv = g_inv[bz];
        factor = inv * inv * 65536.f;
    }
    const int quad = l >> 2, tq = l & 3;
#pragma unroll
    for (int i = 0; i < 4; i++) {
#pragma unroll
        for (int half = 0; half < 2; half++) {
            const int rr = m0 + wm * 64 + i * 16 + quad + half * 8;
            float bvv = 0.f;
            if (EPI == 1) bvv = bias[rr];
#pragma unroll
            for (int j = 0; j < 4; j++) {
                const int col = n0 + wn * 32 + j * 8 + tq * 2;
                float v0 = acc[i][j][half * 2 + 0];
                float v1 = acc[i][j][half * 2 + 1];
                if (EPI == 0) {
                    // Shat = relu(acc/256)^2  (fp16-range-safe scaled S)
                    v0 = fmaxf(v0 * 0.00390625f, 0.f); v0 *= v0;
                    v1 = fmaxf(v1 * 0.00390625f, 0.f); v1 *= v1;
                    size_t base = (size_t)bz * HWDIM * HWDIM + (size_t)rr * HWDIM + col;
                    *(uint32_t*)(g_Shat + base) = packhf(v0, v1);
                } else if (EPI == 1) {
                    float2 vv; vv.x = v0 + bvv; vv.y = v1 + bvv;
                    *(float2*)(g_T + (size_t)bz * PB + (size_t)rr * HWDIM + col) = vv;
                } else {
                    float2 vv; vv.x = v0 * factor; vv.y = v1 * factor;
                    *(float2*)(outY + (size_t)bz * PB + (size_t)rr * CDIM + col) = vv;
                }
            }
        }
    }
#undef LOAD_STAGE
}

// ---------------------------------------------------------------------------
// Host launch
// ---------------------------------------------------------------------------
extern "C" void kernel_launch(void* const* d_in, const int* in_sizes, int n_in,
                              void* d_out, int out_size)
{
    const float* x    = (const float*)d_in[0];
    const float* W    = (const float*)d_in[1];
    const float* bias = (const float*)d_in[2];
    float* out        = (float*)d_out;

    void *pXhi, *pXlo, *pXThi, *pXTlo, *pWhi, *pWlo, *pShat, *pTThi, *pT;
    cudaGetSymbolAddress(&pXhi,  g_Xhi);
    cudaGetSymbolAddress(&pXlo,  g_Xlo);
    cudaGetSymbolAddress(&pXThi, g_XThi);
    cudaGetSymbolAddress(&pXTlo, g_XTlo);
    cudaGetSymbolAddress(&pWhi,  g_Whi);
    cudaGetSymbolAddress(&pWlo,  g_Wlo);
    cudaGetSymbolAddress(&pShat, g_Shat);
    cudaGetSymbolAddress(&pTThi, g_TThi);
    cudaGetSymbolAddress(&pT,    g_T);

    static bool attr_done = false;
    if (!attr_done) {
        cudaFuncSetAttribute(mm_fp16<0, 2>, cudaFuncAttributeMaxDynamicSharedMemorySize, SMEM2);
        cudaFuncSetAttribute(mm_fp16<1, 3>, cudaFuncAttributeMaxDynamicSharedMemorySize, SMEM3);
        cudaFuncSetAttribute(mm_fp16<2, 1>, cudaFuncAttributeMaxDynamicSharedMemorySize, SMEM1);
        attr_done = true;
    }

    // 1) norm
    sumsq_kernel<<<BATCH, 512>>>(x);

    // 2) splits + transposes
    split_flat<<<(BATCH * PB / 4 + 255) / 256, 256>>>((const float4*)x, (uint2*)pXhi, (uint2*)pXlo, BATCH * PB / 4);
    split_flat<<<(CDIM * CDIM / 4 + 255) / 256, 256>>>((const float4*)W, (uint2*)pWhi, (uint2*)pWlo, CDIM * CDIM / 4);
    {   // XT = transpose(x viewed [256,2304]) -> [2304,256] fp16 hi/lo
        dim3 g(HWDIM / 32, CDIM / 32, BATCH);
        transpose_split<<<g, dim3(32, 8)>>>(x, (__half*)pXThi, (__half*)pXTlo, CDIM, HWDIM);
    }

    // 3) GEMM2 (3-term): T[o,p] = W @ x2 + bias   (M=256, N=2304, K=256)
    mm_fp16<1, 3><<<dim3(HWDIM / 128, CDIM / 128, BATCH), 256, SMEM3>>>(
        (const __half*)pWhi, (const __half*)pWlo,
        (const __half*)pXThi, (const __half*)pXTlo,
        CDIM, CDIM, 0, (size_t)PB, CDIM, bias, nullptr);

    // 4) TT = transpose(T viewed [2304,256]) -> [256,2304] fp16
    {
        dim3 g(CDIM / 32, HWDIM / 32, BATCH);
        transpose_cast<<<g, dim3(32, 8)>>>((const float*)pT, (__half*)pTThi, HWDIM, CDIM);
    }

    // 5) GEMM1 (2-term): Shat = relu(((x1 @ x2hi))/256)^2   (M=N=2304, K=256)
    mm_fp16<0, 2><<<dim3(HWDIM / 128, HWDIM / 128, BATCH), 256, SMEM2>>>(
        (const __half*)pXhi, (const __half*)pXlo,
        (const __half*)pXThi, nullptr,
        CDIM, CDIM, (size_t)PB, (size_t)PB, CDIM, nullptr, nullptr);

    // 6) GEMM3 (1-term): Y = Shat @ Tview * inv^2*2^16 -> out  (M=2304, N=256, K=2304)
    mm_fp16<2, 1><<<dim3(CDIM / 128, HWDIM / 128, BATCH), 256, SMEM1>>>(
        (const __half*)pShat, nullptr, (const __half*)pTThi, nullptr,
        HWDIM, HWDIM, (size_t)HWDIM * HWDIM, (size_t)PB, HWDIM, nullptr, out);
}

// round 11
// speedup vs baseline: 2.3399x; 1.2149x over previous
#include <cuda_runtime.h>
#include <cuda_fp16.h>
#include <cstdint>

#define BATCH 16
#define CDIM 256
#define HWDIM 2304
#define PB (CDIM * HWDIM)

#define NST 3
#define STG2 30720u                 // Ahi+Alo+Bhi, 128 rows x 80B each
#define STG1 20480u                 // Ahi+Bhi
#define SMEM2 (NST * STG2)          // 92160
#define SMEM1 (NST * STG1)          // 61440

// ---------------------------------------------------------------------------
// Device scratch (allocation-free)
// ---------------------------------------------------------------------------
__device__ float g_inv[BATCH];
__device__ float g_T[(size_t)BATCH * PB];
__device__ __align__(1024) __half g_Xhi[(size_t)BATCH * PB];
__device__ __align__(1024) __half g_XThi[(size_t)BATCH * PB];
__device__ __align__(1024) __half g_Whi[CDIM * CDIM];
__device__ __align__(1024) __half g_Wlo[CDIM * CDIM];
__device__ __align__(1024) __half g_Shat[(size_t)BATCH * HWDIM * HWDIM];  // 170MB, scaled S
__device__ __align__(1024) __half g_TThi[(size_t)BATCH * PB];

// ---------------------------------------------------------------------------
// per-batch 1/||x||^2
// ---------------------------------------------------------------------------
__global__ void sumsq_kernel(const float* __restrict__ x) {
    const int b = blockIdx.x;
    const float4* p = (const float4*)(x + (size_t)b * PB);
    float s = 0.f;
    for (int i = threadIdx.x; i < PB / 4; i += blockDim.x) {
        float4 v = p[i];
        s += v.x * v.x + v.y * v.y + v.z * v.z + v.w * v.w;
    }
    __shared__ float red[512];
    red[threadIdx.x] = s;
    __syncthreads();
    for (int off = blockDim.x >> 1; off > 0; off >>= 1) {
        if (threadIdx.x < (unsigned)off) red[threadIdx.x] += red[threadIdx.x + off];
        __syncthreads();
    }
    if (threadIdx.x == 0) g_inv[b] = 1.0f / red[0];
}

// ---------------------------------------------------------------------------
// fp16 helpers
// ---------------------------------------------------------------------------
__device__ __forceinline__ uint32_t packhf(float a, float b) {
    __half ha = __float2half_rn(a), hb = __float2half_rn(b);
    return (uint32_t)__half_as_ushort(ha) | ((uint32_t)__half_as_ushort(hb) << 16);
}

// f32 -> fp16 cast (flat, hi only)
__global__ void cast_flat(const float4* __restrict__ in, uint2* __restrict__ hi, int n4) {
    int i = blockIdx.x * blockDim.x + threadIdx.x;
    if (i >= n4) return;
    float4 v = in[i];
    uint2 hp;
    hp.x = packhf(v.x, v.y);
    hp.y = packhf(v.z, v.w);
    hi[i] = hp;
}

// f32 -> fp16 hi/lo split (flat) — used for W only
__global__ void split_flat(const float4* __restrict__ in,
                           uint2* __restrict__ hi, uint2* __restrict__ lo, int n4) {
    int i = blockIdx.x * blockDim.x + threadIdx.x;
    if (i >= n4) return;
    float4 v = in[i];
    __half h0 = __float2half_rn(v.x), h1 = __float2half_rn(v.y);
    __half h2 = __float2half_rn(v.z), h3 = __float2half_rn(v.w);
    uint2 hp, lp;
    hp.x = (uint32_t)__half_as_ushort(h0) | ((uint32_t)__half_as_ushort(h1) << 16);
    hp.y = (uint32_t)__half_as_ushort(h2) | ((uint32_t)__half_as_ushort(h3) << 16);
    lp.x = packhf(v.x - __half2float(h0), v.y - __half2float(h1));
    lp.y = packhf(v.z - __half2float(h2), v.w - __half2float(h3));
    hi[i] = hp;
    lo[i] = lp;
}

// per-batch transpose + fp16 cast (hi only): [rows,cols] f32 -> [cols,rows]
__global__ void transpose_cast(const float* __restrict__ in,
                               __half* __restrict__ hi, int rows, int cols) {
    __shared__ float t[32][33];
    const size_t off = (size_t)blockIdx.z * rows * cols;
    const int c0 = blockIdx.x * 32, r0 = blockIdx.y * 32;
    const int x = threadIdx.x, y0 = threadIdx.y;
#pragma unroll
    for (int yy = y0; yy < 32; yy += 8)
        t[yy][x] = in[off + (size_t)(r0 + yy) * cols + c0 + x];
    __syncthreads();
#pragma unroll
    for (int yy = y0; yy < 32; yy += 8)
        hi[off + (size_t)(c0 + yy) * rows + r0 + x] = __float2half_rn(t[x][yy]);
}

// ---------------------------------------------------------------------------
// PTX helpers (sm_80 baseline — compiles on plain compute_103)
// ---------------------------------------------------------------------------
__device__ __forceinline__ uint32_t s2u(const void* p) {
    uint32_t a;
    asm("{ .reg .u64 t; cvta.to.shared.u64 t, %1; cvt.u32.u64 %0, t; }" : "=r"(a) : "l"(p));
    return a;
}
__device__ __forceinline__ void cp16(uint32_t d, const void* g) {
    asm volatile("cp.async.cg.shared.global [%0], [%1], 16;" :: "r"(d), "l"(g));
}
#define LDM4(r, addr) \
    asm volatile("ldmatrix.sync.aligned.m8n8.x4.shared.b16 {%0,%1,%2,%3}, [%4];" \
        : "=r"((r)[0]), "=r"((r)[1]), "=r"((r)[2]), "=r"((r)[3]) : "r"(addr))
#define MMAH(c, a0, a1, a2, a3, b0, b1) \
    asm volatile("mma.sync.aligned.m16n8k16.row.col.f32.f16.f16.f32 " \
        "{%0,%1,%2,%3}, {%4,%5,%6,%7}, {%8,%9}, {%0,%1,%2,%3};" \
        : "+f"((c)[0]), "+f"((c)[1]), "+f"((c)[2]), "+f"((c)[3]) \
        : "r"(a0), "r"(a1), "r"(a2), "r"(a3), "r"(b0), "r"(b1))

// ---------------------------------------------------------------------------
// fp16 mma.sync GEMM, CTA 128x128, warp tile 64x32, KC=32
//   D[m,n] = sum_k A[m,k]*B[n,k]   (K-major fp16)
// TERMS=2: ahi*bhi + alo*bhi  (= A*Bhi, A exact)
// TERMS=1: ahi*bhi
// Stage layout (80B row stride): Ahi@0, [Alo@10240,] Bhi@oBh
// EPI 0: Shat = relu(acc/256)^2 -> g_Shat (fp16)
// EPI 1: T = acc + bias[row]     -> g_T (f32, ld 2304)
// EPI 2: Y = acc * inv^2*65536   -> outY (f32, ld 256)
// ---------------------------------------------------------------------------
template <int EPI, int TERMS>
__global__ void __launch_bounds__(256, 2)
mm_fp16(const __half* __restrict__ Ah, const __half* __restrict__ Al,
        const __half* __restrict__ Bh,
        int lda, int ldb, size_t bA, size_t bB, int K,
        const float* __restrict__ bias, float* __restrict__ outY)
{
    constexpr uint32_t STG = (TERMS == 2) ? STG2 : STG1;
    constexpr uint32_t oBh = (TERMS == 2) ? 20480u : 10240u;

    extern __shared__ char smv[];
    const uint32_t sb = s2u(smv);
    const int tid = threadIdx.x;
    const int bz = blockIdx.z;
    const int m0 = blockIdx.y * 128, n0 = blockIdx.x * 128;
    const int w = tid >> 5, l = tid & 31;
    const int wm = w >> 2, wn = w & 3;       // 2 x 4 warps, warp tile 64x32

    // loader: row = tid>>1 (128 rows), 32B chunk = (tid&1) within the 64B row
    const int r = tid >> 1, c = tid & 1;
    const __half* pAh = Ah + (size_t)bz * bA + (size_t)(m0 + r) * lda + c * 16;
    const __half* pAl = (TERMS == 2) ? (Al + (size_t)bz * bA + (size_t)(m0 + r) * lda + c * 16) : nullptr;
    const __half* pBh = Bh + (size_t)bz * bB + (size_t)(n0 + r) * ldb + c * 16;
    const uint32_t dA = sb + r * 80 + c * 32;
    const uint32_t dB = sb + oBh + r * 80 + c * 32;

    // fragment lane addressing (verified scheme, 80B stride)
    const int sub = l >> 3;
    const uint32_t aOff = (uint32_t)((wm * 64 + (sub & 1) * 8 + (l & 7)) * 80 + (sub >> 1) * 16);
    const uint32_t bOff = (uint32_t)(oBh + (wn * 32 + (l >> 4) * 8 + (l & 7)) * 80 + ((l >> 3) & 1) * 16);

    float acc[4][4][4];
#pragma unroll
    for (int i = 0; i < 4; i++)
#pragma unroll
        for (int j = 0; j < 4; j++)
#pragma unroll
            for (int q = 0; q < 4; q++) acc[i][j][q] = 0.f;

#define LOAD_STAGE(kc, slot) do { \
        const uint32_t so = (uint32_t)(slot) * STG; \
        const int ko = (kc) * 32; \
        cp16(dA + so,      pAh + ko); \
        cp16(dA + so + 16, pAh + ko + 8); \
        cp16(dB + so,      pBh + ko); \
        cp16(dB + so + 16, pBh + ko + 8); \
        if (TERMS == 2) { \
            cp16(dA + so + 10240, pAl + ko); \
            cp16(dA + so + 10256, pAl + ko + 8); \
        } \
        asm volatile("cp.async.commit_group;"); \
    } while (0)

    const int KN = K / 32;
    LOAD_STAGE(0, 0);
    LOAD_STAGE(1, 1);

    int slot = 0;
    for (int kc = 0; kc < KN; kc++) {
        asm volatile("cp.async.wait_group 1;");
        __syncthreads();
        if (kc + 2 < KN) LOAD_STAGE(kc + 2, (kc + 2) % NST);
        const uint32_t s0 = sb + slot * STG;
        slot++; if (slot == NST) slot = 0;
#pragma unroll
        for (int ks = 0; ks < 2; ks++) {
            // B fragments: 2 LDM4 -> 4 n8 tiles (hi)
            uint32_t bfh[4][2];
            const uint32_t b0a = s0 + bOff + ks * 32;
#pragma unroll
            for (int p = 0; p < 2; p++) {
                uint32_t t4[4];
                LDM4(t4, b0a + p * (16 * 80));
                bfh[2 * p][0] = t4[0]; bfh[2 * p][1] = t4[1];
                bfh[2 * p + 1][0] = t4[2]; bfh[2 * p + 1][1] = t4[3];
            }
            const uint32_t a0a = s0 + aOff + ks * 32;
#pragma unroll
            for (int i = 0; i < 4; i++) {
                uint32_t ah[4];
                LDM4(ah, a0a + i * 1280);
                if (TERMS == 2) {
                    uint32_t al4[4];
                    LDM4(al4, a0a + i * 1280 + 10240);
#pragma unroll
                    for (int j = 0; j < 4; j++) {
                        MMAH(acc[i][j], ah[0], ah[1], ah[2], ah[3], bfh[j][0], bfh[j][1]);
                        MMAH(acc[i][j], al4[0], al4[1], al4[2], al4[3], bfh[j][0], bfh[j][1]);
                    }
                } else {
#pragma unroll
                    for (int j = 0; j < 4; j++)
                        MMAH(acc[i][j], ah[0], ah[1], ah[2], ah[3], bfh[j][0], bfh[j][1]);
                }
            }
        }
    }

    // epilogue
    float factor = 0.f;
    if (EPI == 2) {
        float inv = g_inv[bz];
        factor = inv * inv * 65536.f;
    }
    const int quad = l >> 2, tq = l & 3;
#pragma unroll
    for (int i = 0; i < 4; i++) {
#pragma unroll
        for (int half = 0; half < 2; half++) {
            const int rr = m0 + wm * 64 + i * 16 + quad + half * 8;
            float bvv = 0.f;
            if (EPI == 1) bvv = bias[rr];
#pragma unroll
            for (int j = 0; j < 4; j++) {
                const int col = n0 + wn * 32 + j * 8 + tq * 2;
                float v0 = acc[i][j][half * 2 + 0];
                float v1 = acc[i][j][half * 2 + 1];
                if (EPI == 0) {
                    // Shat = relu(acc/256)^2  (fp16-range-safe scaled S)
                    v0 = fmaxf(v0 * 0.00390625f, 0.f); v0 *= v0;
                    v1 = fmaxf(v1 * 0.00390625f, 0.f); v1 *= v1;
                    size_t base = (size_t)bz * HWDIM * HWDIM + (size_t)rr * HWDIM + col;
                    *(uint32_t*)(g_Shat + base) = packhf(v0, v1);
                } else if (EPI == 1) {
                    float2 vv; vv.x = v0 + bvv; vv.y = v1 + bvv;
                    *(float2*)(g_T + (size_t)bz * PB + (size_t)rr * HWDIM + col) = vv;
                } else {
                    float2 vv; vv.x = v0 * factor; vv.y = v1 * factor;
                    *(float2*)(outY + (size_t)bz * PB + (size_t)rr * CDIM + col) = vv;
                }
            }
        }
    }
#undef LOAD_STAGE
}

// ---------------------------------------------------------------------------
// Host launch
// ---------------------------------------------------------------------------
extern "C" void kernel_launch(void* const* d_in, const int* in_sizes, int n_in,
                              void* d_out, int out_size)
{
    const float* x    = (const float*)d_in[0];
    const float* W    = (const float*)d_in[1];
    const float* bias = (const float*)d_in[2];
    float* out        = (float*)d_out;

    void *pXhi, *pXThi, *pWhi, *pWlo, *pShat, *pTThi, *pT;
    cudaGetSymbolAddress(&pXhi,  g_Xhi);
    cudaGetSymbolAddress(&pXThi, g_XThi);
    cudaGetSymbolAddress(&pWhi,  g_Whi);
    cudaGetSymbolAddress(&pWlo,  g_Wlo);
    cudaGetSymbolAddress(&pShat, g_Shat);
    cudaGetSymbolAddress(&pTThi, g_TThi);
    cudaGetSymbolAddress(&pT,    g_T);

    static bool attr_done = false;
    if (!attr_done) {
        cudaFuncSetAttribute(mm_fp16<0, 1>, cudaFuncAttributeMaxDynamicSharedMemorySize, SMEM1);
        cudaFuncSetAttribute(mm_fp16<1, 2>, cudaFuncAttributeMaxDynamicSharedMemorySize, SMEM2);
        cudaFuncSetAttribute(mm_fp16<2, 1>, cudaFuncAttributeMaxDynamicSharedMemorySize, SMEM1);
        attr_done = true;
    }

    // 1) norm
    sumsq_kernel<<<BATCH, 512>>>(x);

    // 2) casts / splits / transposes
    cast_flat<<<(BATCH * PB / 4 + 255) / 256, 256>>>((const float4*)x, (uint2*)pXhi, BATCH * PB / 4);
    split_flat<<<(CDIM * CDIM / 4 + 255) / 256, 256>>>((const float4*)W, (uint2*)pWhi, (uint2*)pWlo, CDIM * CDIM / 4);
    {   // XT = transpose(x viewed [256,2304]) -> [2304,256] fp16
        dim3 g(HWDIM / 32, CDIM / 32, BATCH);
        transpose_cast<<<g, dim3(32, 8)>>>(x, (__half*)pXThi, CDIM, HWDIM);
    }

    // 3) GEMM2 (2-term, W exact): T[o,p] = W @ x2hi + bias   (M=256, N=2304, K=256)
    mm_fp16<1, 2><<<dim3(HWDIM / 128, CDIM / 128, BATCH), 256, SMEM2>>>(
        (const __half*)pWhi, (const __half*)pWlo, (const __half*)pXThi,
        CDIM, CDIM, 0, (size_t)PB, CDIM, bias, nullptr);

    // 4) TT = transpose(T viewed [2304,256]) -> [256,2304] fp16
    {
        dim3 g(CDIM / 32, HWDIM / 32, BATCH);
        transpose_cast<<<g, dim3(32, 8)>>>((const float*)pT, (__half*)pTThi, HWDIM, CDIM);
    }

    // 5) GEMM1 (1-term): Shat = relu((x1hi @ x2hi)/256)^2   (M=N=2304, K=256)
    mm_fp16<0, 1><<<dim3(HWDIM / 128, HWDIM / 128, BATCH), 256, SMEM1>>>(
        (const __half*)pXhi, nullptr, (const __half*)pXThi,
        CDIM, CDIM, (size_t)PB, (size_t)PB, CDIM, nullptr, nullptr);

    // 6) GEMM3 (1-term): Y = Shat @ Tview * inv^2*2^16 -> out  (M=2304, N=256, K=2304)
    mm_fp16<2, 1><<<dim3(CDIM / 128, HWDIM / 128, BATCH), 256, SMEM1>>>(
        (const __half*)pShat, nullptr, (const __half*)pTThi,
        HWDIM, HWDIM, (size_t)HWDIM * HWDIM, (size_t)PB, HWDIM, nullptr, out);
}

// round 13
// speedup vs baseline: 2.5278x; 1.0803x over previous
#include <cuda_runtime.h>
#include <cuda_fp16.h>
#include <cstdint>

#define BATCH 16
#define CDIM 256
#define HWDIM 2304
#define PB (CDIM * HWDIM)

#define NST 3
#define STG2 30720u                 // Ahi+Alo+Bhi, 128 rows x 80B each
#define STG1 20480u                 // Ahi+Bhi
#define SMEM2 (NST * STG2)          // 92160
#define SMEM1 (NST * STG1)          // 61440

#define NPART_PER_B 576             // cast_sumsq CTAs per batch
#define NPART (BATCH * NPART_PER_B) // 9216

// ---------------------------------------------------------------------------
// Device scratch (allocation-free)
// ---------------------------------------------------------------------------
__device__ float g_inv[BATCH];
__device__ float g_part[NPART];
__device__ float g_T[(size_t)BATCH * PB];
__device__ __align__(1024) __half g_Xhi[(size_t)BATCH * PB];
__device__ __align__(1024) __half g_XThi[(size_t)BATCH * PB];
__device__ __align__(1024) __half g_Whi[CDIM * CDIM];
__device__ __align__(1024) __half g_Wlo[CDIM * CDIM];
__device__ __align__(1024) __half g_Shat[(size_t)BATCH * HWDIM * HWDIM];  // 170MB, scaled S
__device__ __align__(1024) __half g_TThi[(size_t)BATCH * PB];

// ---------------------------------------------------------------------------
// fp16 helpers
// ---------------------------------------------------------------------------
__device__ __forceinline__ uint32_t packhf(float a, float b) {
    __half ha = __float2half_rn(a), hb = __float2half_rn(b);
    return (uint32_t)__half_as_ushort(ha) | ((uint32_t)__half_as_ushort(hb) << 16);
}

// ---------------------------------------------------------------------------
// fused: f32 -> fp16 cast (flat) + per-CTA partial sum of squares
// grid: NPART CTAs x 256 threads; each CTA covers 256 float4s (fixed partition
// -> deterministic). Batch b owns CTAs [b*576, (b+1)*576).
// ---------------------------------------------------------------------------
__global__ void cast_sumsq(const float4* __restrict__ in, uint2* __restrict__ hi) {
    const int i = blockIdx.x * blockDim.x + threadIdx.x;   // exactly BATCH*PB/4 threads
    float4 v = in[i];
    uint2 hp;
    hp.x = packhf(v.x, v.y);
    hp.y = packhf(v.z, v.w);
    hi[i] = hp;
    float s = v.x * v.x + v.y * v.y + v.z * v.z + v.w * v.w;
    __shared__ float red[256];
    red[threadIdx.x] = s;
    __syncthreads();
    for (int off = 128; off > 0; off >>= 1) {
        if (threadIdx.x < (unsigned)off) red[threadIdx.x] += red[threadIdx.x + off];
        __syncthreads();
    }
    if (threadIdx.x == 0) g_part[blockIdx.x] = red[0];
}

// grid: BATCH x 256 threads; reduce 576 partials per batch -> 1/sum
__global__ void finalize_inv() {
    const int b = blockIdx.x;
    float s = 0.f;
    for (int i = threadIdx.x; i < NPART_PER_B; i += 256)
        s += g_part[b * NPART_PER_B + i];
    __shared__ float red[256];
    red[threadIdx.x] = s;
    __syncthreads();
    for (int off = 128; off > 0; off >>= 1) {
        if (threadIdx.x < (unsigned)off) red[threadIdx.x] += red[threadIdx.x + off];
        __syncthreads();
    }
    if (threadIdx.x == 0) g_inv[b] = 1.0f / red[0];
}

// f32 -> fp16 hi/lo split (flat) — W only
__global__ void split_flat(const float4* __restrict__ in,
                           uint2* __restrict__ hi, uint2* __restrict__ lo, int n4) {
    int i = blockIdx.x * blockDim.x + threadIdx.x;
    if (i >= n4) return;
    float4 v = in[i];
    __half h0 = __float2half_rn(v.x), h1 = __float2half_rn(v.y);
    __half h2 = __float2half_rn(v.z), h3 = __float2half_rn(v.w);
    uint2 hp, lp;
    hp.x = (uint32_t)__half_as_ushort(h0) | ((uint32_t)__half_as_ushort(h1) << 16);
    hp.y = (uint32_t)__half_as_ushort(h2) | ((uint32_t)__half_as_ushort(h3) << 16);
    lp.x = packhf(v.x - __half2float(h0), v.y - __half2float(h1));
    lp.y = packhf(v.z - __half2float(h2), v.w - __half2float(h3));
    hi[i] = hp;
    lo[i] = lp;
}

// per-batch transpose + fp16 cast (hi only): [rows,cols] f32 -> [cols,rows]
__global__ void transpose_cast(const float* __restrict__ in,
                               __half* __restrict__ hi, int rows, int cols) {
    __shared__ float t[32][33];
    const size_t off = (size_t)blockIdx.z * rows * cols;
    const int c0 = blockIdx.x * 32, r0 = blockIdx.y * 32;
    const int x = threadIdx.x, y0 = threadIdx.y;
#pragma unroll
    for (int yy = y0; yy < 32; yy += 8)
        t[yy][x] = in[off + (size_t)(r0 + yy) * cols + c0 + x];
    __syncthreads();
#pragma unroll
    for (int yy = y0; yy < 32; yy += 8)
        hi[off + (size_t)(c0 + yy) * rows + r0 + x] = __float2half_rn(t[x][yy]);
}

// ---------------------------------------------------------------------------
// PTX helpers (sm_80 baseline — compiles on plain compute_103)
// ---------------------------------------------------------------------------
__device__ __forceinline__ uint32_t s2u(const void* p) {
    uint32_t a;
    asm("{ .reg .u64 t; cvta.to.shared.u64 t, %1; cvt.u32.u64 %0, t; }" : "=r"(a) : "l"(p));
    return a;
}
__device__ __forceinline__ void cp16(uint32_t d, const void* g) {
    asm volatile("cp.async.cg.shared.global [%0], [%1], 16;" :: "r"(d), "l"(g));
}
#define LDM4(r, addr) \
    asm volatile("ldmatrix.sync.aligned.m8n8.x4.shared.b16 {%0,%1,%2,%3}, [%4];" \
        : "=r"((r)[0]), "=r"((r)[1]), "=r"((r)[2]), "=r"((r)[3]) : "r"(addr))
#define MMAH(c, a0, a1, a2, a3, b0, b1) \
    asm volatile("mma.sync.aligned.m16n8k16.row.col.f32.f16.f16.f32 " \
        "{%0,%1,%2,%3}, {%4,%5,%6,%7}, {%8,%9}, {%0,%1,%2,%3};" \
        : "+f"((c)[0]), "+f"((c)[1]), "+f"((c)[2]), "+f"((c)[3]) \
        : "r"(a0), "r"(a1), "r"(a2), "r"(a3), "r"(b0), "r"(b1))

// ---------------------------------------------------------------------------
// fp16 mma.sync GEMM, CTA 128x128, warp tile 64x32, KC=32
//   D[m,n] = sum_k A[m,k]*B[n,k]   (K-major fp16)
// TERMS=2: ahi*bhi + alo*bhi  (= A*Bhi, A exact)
// TERMS=1: ahi*bhi
// Stage layout (80B row stride): Ahi@0, [Alo@10240,] Bhi@oBh
// EPI 0: Shat = relu(acc/256)^2 -> g_Shat (fp16)
// EPI 1: T = acc + bias[row]     -> g_T (f32, ld 2304)
// EPI 2: Y = acc * inv^2*65536   -> outY (f32, ld 256)
// ---------------------------------------------------------------------------
template <int EPI, int TERMS>
__global__ void __launch_bounds__(256, 2)
mm_fp16(const __half* __restrict__ Ah, const __half* __restrict__ Al,
        const __half* __restrict__ Bh,
        int lda, int ldb, size_t bA, size_t bB, int K,
        const float* __restrict__ bias, float* __restrict__ outY)
{
    constexpr uint32_t STG = (TERMS == 2) ? STG2 : STG1;
    constexpr uint32_t oBh = (TERMS == 2) ? 20480u : 10240u;

    extern __shared__ char smv[];
    const uint32_t sb = s2u(smv);
    const int tid = threadIdx.x;
    const int bz = blockIdx.z;
    const int m0 = blockIdx.y * 128, n0 = blockIdx.x * 128;
    const int w = tid >> 5, l = tid & 31;
    const int wm = w >> 2, wn = w & 3;       // 2 x 4 warps, warp tile 64x32

    // loader: row = tid>>1 (128 rows), 32B chunk = (tid&1) within the 64B row
    const int r = tid >> 1, c = tid & 1;
    const __half* pAh = Ah + (size_t)bz * bA + (size_t)(m0 + r) * lda + c * 16;
    const __half* pAl = (TERMS == 2) ? (Al + (size_t)bz * bA + (size_t)(m0 + r) * lda + c * 16) : nullptr;
    const __half* pBh = Bh + (size_t)bz * bB + (size_t)(n0 + r) * ldb + c * 16;
    const uint32_t dA = sb + r * 80 + c * 32;
    const uint32_t dB = sb + oBh + r * 80 + c * 32;

    // fragment lane addressing (verified scheme, 80B stride)
    const int sub = l >> 3;
    const uint32_t aOff = (uint32_t)((wm * 64 + (sub & 1) * 8 + (l & 7)) * 80 + (sub >> 1) * 16);
    const uint32_t bOff = (uint32_t)(oBh + (wn * 32 + (l >> 4) * 8 + (l & 7)) * 80 + ((l >> 3) & 1) * 16);

    float acc[4][4][4];
#pragma unroll
    for (int i = 0; i < 4; i++)
#pragma unroll
        for (int j = 0; j < 4; j++)
#pragma unroll
            for (int q = 0; q < 4; q++) acc[i][j][q] = 0.f;

#define LOAD_STAGE(kc, slot) do { \
        const uint32_t so = (uint32_t)(slot) * STG; \
        const int ko = (kc) * 32; \
        cp16(dA + so,      pAh + ko); \
        cp16(dA + so + 16, pAh + ko + 8); \
        cp16(dB + so,      pBh + ko); \
        cp16(dB + so + 16, pBh + ko + 8); \
        if (TERMS == 2) { \
            cp16(dA + so + 10240, pAl + ko); \
            cp16(dA + so + 10256, pAl + ko + 8); \
        } \
        asm volatile("cp.async.commit_group;"); \
    } while (0)

    const int KN = K / 32;
    LOAD_STAGE(0, 0);
    LOAD_STAGE(1, 1);

    int slot = 0;
    for (int kc = 0; kc < KN; kc++) {
        asm volatile("cp.async.wait_group 1;");
        __syncthreads();
        if (kc + 2 < KN) LOAD_STAGE(kc + 2, (kc + 2) % NST);
        const uint32_t s0 = sb + slot * STG;
        slot++; if (slot == NST) slot = 0;
#pragma unroll
        for (int ks = 0; ks < 2; ks++) {
            // B fragments: 2 LDM4 -> 4 n8 tiles (hi)
            uint32_t bfh[4][2];
            const uint32_t b0a = s0 + bOff + ks * 32;
#pragma unroll
            for (int p = 0; p < 2; p++) {
                uint32_t t4[4];
                LDM4(t4, b0a + p * (16 * 80));
                bfh[2 * p][0] = t4[0]; bfh[2 * p][1] = t4[1];
                bfh[2 * p + 1][0] = t4[2]; bfh[2 * p + 1][1] = t4[3];
            }
            const uint32_t a0a = s0 + aOff + ks * 32;
#pragma unroll
            for (int i = 0; i < 4; i++) {
                uint32_t ah[4];
                LDM4(ah, a0a + i * 1280);
                if (TERMS == 2) {
                    uint32_t al4[4];
                    LDM4(al4, a0a + i * 1280 + 10240);
#pragma unroll
                    for (int j = 0; j < 4; j++) {
                        MMAH(acc[i][j], ah[0], ah[1], ah[2], ah[3], bfh[j][0], bfh[j][1]);
                        MMAH(acc[i][j], al4[0], al4[1], al4[2], al4[3], bfh[j][0], bfh[j][1]);
                    }
                } else {
#pragma unroll
                    for (int j = 0; j < 4; j++)
                        MMAH(acc[i][j], ah[0], ah[1], ah[2], ah[3], bfh[j][0], bfh[j][1]);
                }
            }
        }
    }

    // epilogue
    float factor = 0.f;
    if (EPI == 2) {
        float inv = g_inv[bz];
        factor = inv * inv * 65536.f;
    }
    const int quad = l >> 2, tq = l & 3;
#pragma unroll
    for (int i = 0; i < 4; i++) {
#pragma unroll
        for (int half = 0; half < 2; half++) {
            const int rr = m0 + wm * 64 + i * 16 + quad + half * 8;
            float bvv = 0.f;
            if (EPI == 1) bvv = bias[rr];
#pragma unroll
            for (int j = 0; j < 4; j++) {
                const int col = n0 + wn * 32 + j * 8 + tq * 2;
                float v0 = acc[i][j][half * 2 + 0];
                float v1 = acc[i][j][half * 2 + 1];
                if (EPI == 0) {
                    // Shat = relu(acc/256)^2  (fp16-range-safe scaled S)
                    v0 = fmaxf(v0 * 0.00390625f, 0.f); v0 *= v0;
                    v1 = fmaxf(v1 * 0.00390625f, 0.f); v1 *= v1;
                    size_t base = (size_t)bz * HWDIM * HWDIM + (size_t)rr * HWDIM + col;
                    *(uint32_t*)(g_Shat + base) = packhf(v0, v1);
                } else if (EPI == 1) {
                    float2 vv; vv.x = v0 + bvv; vv.y = v1 + bvv;
                    *(float2*)(g_T + (size_t)bz * PB + (size_t)rr * HWDIM + col) = vv;
                } else {
                    float2 vv; vv.x = v0 * factor; vv.y = v1 * factor;
                    *(float2*)(outY + (size_t)bz * PB + (size_t)rr * CDIM + col) = vv;
                }
            }
        }
    }
#undef LOAD_STAGE
}

// ---------------------------------------------------------------------------
// Host launch
// ---------------------------------------------------------------------------
extern "C" void kernel_launch(void* const* d_in, const int* in_sizes, int n_in,
                              void* d_out, int out_size)
{
    const float* x    = (const float*)d_in[0];
    const float* W    = (const float*)d_in[1];
    const float* bias = (const float*)d_in[2];
    float* out        = (float*)d_out;

    void *pXhi, *pXThi, *pWhi, *pWlo, *pShat, *pTThi, *pT;
    cudaGetSymbolAddress(&pXhi,  g_Xhi);
    cudaGetSymbolAddress(&pXThi, g_XThi);
    cudaGetSymbolAddress(&pWhi,  g_Whi);
    cudaGetSymbolAddress(&pWlo,  g_Wlo);
    cudaGetSymbolAddress(&pShat, g_Shat);
    cudaGetSymbolAddress(&pTThi, g_TThi);
    cudaGetSymbolAddress(&pT,    g_T);

    static bool attr_done = false;
    if (!attr_done) {
        cudaFuncSetAttribute(mm_fp16<0, 1>, cudaFuncAttributeMaxDynamicSharedMemorySize, SMEM1);
        cudaFuncSetAttribute(mm_fp16<1, 2>, cudaFuncAttributeMaxDynamicSharedMemorySize, SMEM2);
        cudaFuncSetAttribute(mm_fp16<2, 1>, cudaFuncAttributeMaxDynamicSharedMemorySize, SMEM1);
        attr_done = true;
    }

    // 1) fused x cast + per-CTA sumsq partials, then 1/||x||^2 per batch
    cast_sumsq<<<NPART, 256>>>((const float4*)x, (uint2*)pXhi);
    finalize_inv<<<BATCH, 256>>>();

    // 2) W split + XT transpose
    split_flat<<<(CDIM * CDIM / 4 + 255) / 256, 256>>>((const float4*)W, (uint2*)pWhi, (uint2*)pWlo, CDIM * CDIM / 4);
    {   // XT = transpose(x viewed [256,2304]) -> [2304,256] fp16
        dim3 g(HWDIM / 32, CDIM / 32, BATCH);
        transpose_cast<<<g, dim3(32, 8)>>>(x, (__half*)pXThi, CDIM, HWDIM);
    }

    // 3) GEMM2 (2-term, W exact): T[o,p] = W @ x2hi + bias   (M=256, N=2304, K=256)
    mm_fp16<1, 2><<<dim3(HWDIM / 128, CDIM / 128, BATCH), 256, SMEM2>>>(
        (const __half*)pWhi, (const __half*)pWlo, (const __half*)pXThi,
        CDIM, CDIM, 0, (size_t)PB, CDIM, bias, nullptr);

    // 4) TT = transpose(T viewed [2304,256]) -> [256,2304] fp16
    {
        dim3 g(CDIM / 32, HWDIM / 32, BATCH);
        transpose_cast<<<g, dim3(32, 8)>>>((const float*)pT, (__half*)pTThi, HWDIM, CDIM);
    }

    // 5) GEMM1 (1-term): Shat = relu((x1hi @ x2hi)/256)^2   (M=N=2304, K=256)
    mm_fp16<0, 1><<<dim3(HWDIM / 128, HWDIM / 128, BATCH), 256, SMEM1>>>(
        (const __half*)pXhi, nullptr, (const __half*)pXThi,
        CDIM, CDIM, (size_t)PB, (size_t)PB, CDIM, nullptr, nullptr);

    // 6) GEMM3 (1-term): Y = Shat @ Tview * inv^2*2^16 -> out  (M=2304, N=256, K=2304)
    mm_fp16<2, 1><<<dim3(CDIM / 128, HWDIM / 128, BATCH), 256, SMEM1>>>(
        (const __half*)pShat, nullptr, (const __half*)pTThi,
        HWDIM, HWDIM, (size_t)HWDIM * HWDIM, (size_t)PB, HWDIM, nullptr, out);
}